// round 3
// baseline (speedup 1.0000x reference)
#include <cuda_runtime.h>
#include <mma.h>
#include <cstdint>

using namespace nvcuda;

// ---------------------------------------------------------------------------
// LSTM cell, fused, wmma TF32 (m16n16k8).
//   gates = [x|h] @ W4^T + b4 ; c' = sig(f)*c + sig(i)*tanh(g)
//   h' = sig(o)*tanh(c') ; y = h' @ Wy^T + b_y
// Out: [y | h' | c'], each B x 128 fp32.
// ---------------------------------------------------------------------------

#define B_ROWS   131072
#define K_DIM    256
#define N_GATES  512
#define H_DIM    128

#define M_TILE   64
#define KC       32
#define NCHUNK   (K_DIM / KC)         // 8

// Phase-1 strides (floats); rows are 32B-aligned multiples (40*4=160B).
#define SA_STRIDE 40
#define SW_STRIDE 40
#define SA_FLOATS (2 * M_TILE * SA_STRIDE)     // 5120
#define SW_FLOATS (2 * N_GATES * SW_STRIDE)    // 40960
#define SMEM_FLOATS (SA_FLOATS + SW_FLOATS)    // 46080
#define SMEM_BYTES  (SMEM_FLOATS * 4)          // 184320

// Phase-2 layout (all within SMEM_FLOATS):
//   smC  [64][520]  @ 0        (gates fp32)         33280 floats
//   smH  [64][136]  @ 33280    (h' tf32-rounded)     8704 floats  -> 41984
//   smWy [128][136] @ 0        (after smC dead)     17408 floats
//   smY  [64][136]  @ 17408                          8704 floats  -> 26112
#define SC_STRIDE 520
#define HS_STRIDE 136
#define SMH_BASE  (M_TILE * SC_STRIDE)         // 33280
#define SMWY_BASE 0
#define SMY_BASE  (H_DIM * HS_STRIDE)          // 17408

__device__ __align__(16) float g_W4t[N_GATES * K_DIM];   // [512][256] gate-major i,f,o,g
__device__ __align__(16) float g_Wyt[H_DIM * H_DIM];     // [128][128]

__device__ __forceinline__ uint32_t f2tf32(float x) {
    uint32_t r;
    asm("cvt.rna.tf32.f32 %0, %1;" : "=r"(r) : "f"(x));
    return r;
}

__device__ __forceinline__ void cp16(uint32_t dst, const void* src) {
    asm volatile("cp.async.cg.shared.global [%0], [%1], 16;"
                 :: "r"(dst), "l"(src) : "memory");
}
__device__ __forceinline__ void cp_commit() {
    asm volatile("cp.async.commit_group;" ::: "memory");
}
template<int N> __device__ __forceinline__ void cp_wait() {
    asm volatile("cp.async.wait_group %0;" :: "n"(N) : "memory");
}

__device__ __forceinline__ float sigm(float v) {
    return __fdividef(1.0f, 1.0f + __expf(-v));
}
__device__ __forceinline__ float tanh_fast(float v) {
    float e = __expf(2.0f * v);
    return 1.0f - __fdividef(2.0f, e + 1.0f);
}

// ---------------------------------------------------------------------------
__global__ void prep_kernel(const float* __restrict__ Wi, const float* __restrict__ Wf,
                            const float* __restrict__ Wo, const float* __restrict__ Wg,
                            const float* __restrict__ Wy) {
    int idx = blockIdx.x * blockDim.x + threadIdx.x;
    if (idx < N_GATES * K_DIM) {
        int n = idx >> 8;
        int k = idx & 255;
        const float* W = (n < 128) ? Wi : (n < 256) ? Wf : (n < 384) ? Wo : Wg;
        g_W4t[idx] = __uint_as_float(f2tf32(W[(n & 127) * K_DIM + k]));
    } else {
        int j = idx - N_GATES * K_DIM;
        if (j < H_DIM * H_DIM)
            g_Wyt[j] = __uint_as_float(f2tf32(Wy[j]));
    }
}

// ---------------------------------------------------------------------------
// 256 threads = 8 warps. GEMM1 warp grid 2(M) x 4(N): 32 rows x 128 cols each.
// GEMM2 warp grid 2(M) x 4(N): 32 rows x 32 cols each.
// ---------------------------------------------------------------------------
typedef wmma::fragment<wmma::matrix_a, 16, 16, 8, wmma::precision::tf32, wmma::row_major> FragA;
typedef wmma::fragment<wmma::matrix_b, 16, 16, 8, wmma::precision::tf32, wmma::col_major> FragB;
typedef wmma::fragment<wmma::accumulator, 16, 16, 8, float> FragC;

__global__ void __launch_bounds__(256, 1)
lstm_fused_kernel(const float* __restrict__ x, const float* __restrict__ hidden,
                  const float* __restrict__ cell,
                  const float* __restrict__ b_i, const float* __restrict__ b_f,
                  const float* __restrict__ b_o, const float* __restrict__ b_g,
                  const float* __restrict__ b_y, float* __restrict__ out) {
    extern __shared__ float sm[];
    float* smA = sm;
    float* smW = sm + SA_FLOATS;

    const int tid  = threadIdx.x;
    const int wid  = tid >> 5;
    const int mw   = wid & 1;
    const int nw   = wid >> 1;
    const int row0 = blockIdx.x * M_TILE;

    const uint32_t sA_u = (uint32_t)__cvta_generic_to_shared(smA);
    const uint32_t sW_u = (uint32_t)__cvta_generic_to_shared(smW);

    FragC acc[2][8];
    #pragma unroll
    for (int mi = 0; mi < 2; mi++)
        #pragma unroll
        for (int n8 = 0; n8 < 8; n8++)
            wmma::fill_fragment(acc[mi][n8], 0.0f);

    auto issue_chunk = [&](int kc, int buf) {
        #pragma unroll
        for (int i = 0; i < 2; i++) {          // A: 64 rows x 8 quads
            int idx = tid + i * 256;
            int r   = idx >> 3;
            int c4  = idx & 7;
            int colg = kc * KC + c4 * 4;
            const float* src = (colg < 128)
                ? (x + (size_t)(row0 + r) * 128 + colg)
                : (hidden + (size_t)(row0 + r) * 128 + (colg - 128));
            cp16(sA_u + (uint32_t)(((buf * M_TILE + r) * SA_STRIDE + c4 * 4) * 4), src);
        }
        #pragma unroll
        for (int i = 0; i < 16; i++) {         // W: 512 rows x 8 quads
            int idx = tid + i * 256;
            int n   = idx >> 3;
            int c4  = idx & 7;
            const float* src = g_W4t + n * K_DIM + kc * KC + c4 * 4;
            cp16(sW_u + (uint32_t)(((buf * N_GATES + n) * SW_STRIDE + c4 * 4) * 4), src);
        }
        cp_commit();
    };

    issue_chunk(0, 0);

    for (int kc = 0; kc < NCHUNK; kc++) {
        if (kc + 1 < NCHUNK) {
            issue_chunk(kc + 1, (kc + 1) & 1);
            cp_wait<1>();
        } else {
            cp_wait<0>();
        }
        __syncthreads();

        const float* Ab = smA + (kc & 1) * M_TILE * SA_STRIDE;
        const float* Wb = smW + (kc & 1) * N_GATES * SW_STRIDE;

        #pragma unroll
        for (int kk = 0; kk < KC; kk += 8) {
            FragA af[2];
            #pragma unroll
            for (int mi = 0; mi < 2; mi++) {
                wmma::load_matrix_sync(af[mi], Ab + (mw * 32 + mi * 16) * SA_STRIDE + kk, SA_STRIDE);
                #pragma unroll
                for (int e = 0; e < af[mi].num_elements; e++)
                    af[mi].x[e] = wmma::__float_to_tf32(af[mi].x[e]);
            }
            #pragma unroll
            for (int n8 = 0; n8 < 8; n8++) {
                FragB bf;   // B[k][n] = W4t[n][k] -> col_major, ld = SW_STRIDE
                wmma::load_matrix_sync(bf, Wb + (nw * 128 + n8 * 16) * SW_STRIDE + kk, SW_STRIDE);
                wmma::mma_sync(acc[0][n8], af[0], bf, acc[0][n8]);
                wmma::mma_sync(acc[1][n8], af[1], bf, acc[1][n8]);
            }
        }
        __syncthreads();   // protect buffers for next chunk's cp.async
    }

    // ---- store gates to smem --------------------------------------------
    float* smC = sm;
    float* smH = sm + SMH_BASE;
    #pragma unroll
    for (int mi = 0; mi < 2; mi++)
        #pragma unroll
        for (int n8 = 0; n8 < 8; n8++)
            wmma::store_matrix_sync(smC + (mw * 32 + mi * 16) * SC_STRIDE + nw * 128 + n8 * 16,
                                    acc[mi][n8], SC_STRIDE, wmma::mem_row_major);
    __syncthreads();

    // ---- epilogue 1: gates -> c', h' ------------------------------------
    float* out_y = out;
    float* out_h = out + (size_t)B_ROWS * 128;
    float* out_c = out + (size_t)2 * B_ROWS * 128;

    {
        int r = tid >> 2;              // 0..63
        int q = tid & 3;               // 0..3 -> col group of 32
        size_t rg = (size_t)(row0 + r);
        const float* Crow = smC + r * SC_STRIDE;
        #pragma unroll
        for (int jj = 0; jj < 32; jj += 4) {
            int j = q * 32 + jj;
            float4 g_i = *reinterpret_cast<const float4*>(Crow + j);
            float4 g_f = *reinterpret_cast<const float4*>(Crow + 128 + j);
            float4 g_o = *reinterpret_cast<const float4*>(Crow + 256 + j);
            float4 g_g = *reinterpret_cast<const float4*>(Crow + 384 + j);
            float4 bi4 = *reinterpret_cast<const float4*>(b_i + j);
            float4 bf4 = *reinterpret_cast<const float4*>(b_f + j);
            float4 bo4 = *reinterpret_cast<const float4*>(b_o + j);
            float4 bg4 = *reinterpret_cast<const float4*>(b_g + j);
            float4 c4  = *reinterpret_cast<const float4*>(cell + rg * 128 + j);

            float iv[4] = {g_i.x + bi4.x, g_i.y + bi4.y, g_i.z + bi4.z, g_i.w + bi4.w};
            float fv[4] = {g_f.x + bf4.x, g_f.y + bf4.y, g_f.z + bf4.z, g_f.w + bf4.w};
            float ov[4] = {g_o.x + bo4.x, g_o.y + bo4.y, g_o.z + bo4.z, g_o.w + bo4.w};
            float gv[4] = {g_g.x + bg4.x, g_g.y + bg4.y, g_g.z + bg4.z, g_g.w + bg4.w};
            float co[4] = {c4.x, c4.y, c4.z, c4.w};

            float4 cn, hn, hr;
            float cc[4], hh[4];
            #pragma unroll
            for (int e = 0; e < 4; e++) {
                float ig = sigm(iv[e]);
                float fg = sigm(fv[e]);
                float og = sigm(ov[e]);
                float gg = tanh_fast(gv[e]);
                cc[e] = fg * co[e] + ig * gg;
                hh[e] = og * tanh_fast(cc[e]);
            }
            cn.x = cc[0]; cn.y = cc[1]; cn.z = cc[2]; cn.w = cc[3];
            hn.x = hh[0]; hn.y = hh[1]; hn.z = hh[2]; hn.w = hh[3];
            hr.x = __uint_as_float(f2tf32(hh[0]));
            hr.y = __uint_as_float(f2tf32(hh[1]));
            hr.z = __uint_as_float(f2tf32(hh[2]));
            hr.w = __uint_as_float(f2tf32(hh[3]));
            *reinterpret_cast<float4*>(out_c + rg * 128 + j) = cn;
            *reinterpret_cast<float4*>(out_h + rg * 128 + j) = hn;
            *reinterpret_cast<float4*>(smH + r * HS_STRIDE + j) = hr;
        }
    }
    __syncthreads();   // smC reads done; smH complete

    // ---- stage Wy over dead smC: 128 rows x 32 quads = 4096 slots --------
    float* smWy = sm + SMWY_BASE;
    #pragma unroll
    for (int i = 0; i < 16; i++) {
        int idx = tid + i * 256;
        int n   = idx >> 5;            // 0..127
        int c4  = idx & 31;            // 0..31
        float4 v = *reinterpret_cast<const float4*>(g_Wyt + n * H_DIM + c4 * 4);
        *reinterpret_cast<float4*>(smWy + n * HS_STRIDE + c4 * 4) = v;
    }
    __syncthreads();

    // ---- GEMM2: y = h' @ Wy^T ; warp tile 32x32 --------------------------
    float* smY = sm + SMY_BASE;
    {
        FragC acc2[2][2];
        #pragma unroll
        for (int mi = 0; mi < 2; mi++)
            #pragma unroll
            for (int ni = 0; ni < 2; ni++)
                wmma::fill_fragment(acc2[mi][ni], 0.0f);

        #pragma unroll
        for (int kk = 0; kk < H_DIM; kk += 8) {
            FragA af[2];
            #pragma unroll
            for (int mi = 0; mi < 2; mi++)
                wmma::load_matrix_sync(af[mi], smH + (mw * 32 + mi * 16) * HS_STRIDE + kk, HS_STRIDE);
            #pragma unroll
            for (int ni = 0; ni < 2; ni++) {
                FragB bf;
                wmma::load_matrix_sync(bf, smWy + (nw * 32 + ni * 16) * HS_STRIDE + kk, HS_STRIDE);
                wmma::mma_sync(acc2[0][ni], af[0], bf, acc2[0][ni]);
                wmma::mma_sync(acc2[1][ni], af[1], bf, acc2[1][ni]);
            }
        }
        #pragma unroll
        for (int mi = 0; mi < 2; mi++)
            #pragma unroll
            for (int ni = 0; ni < 2; ni++)
                wmma::store_matrix_sync(smY + (mw * 32 + mi * 16) * HS_STRIDE + nw * 32 + ni * 16,
                                        acc2[mi][ni], HS_STRIDE, wmma::mem_row_major);
    }
    __syncthreads();

    // ---- epilogue 2: y + b_y --------------------------------------------
    {
        int r = tid >> 2;
        int q = tid & 3;
        size_t rg = (size_t)(row0 + r);
        #pragma unroll
        for (int jj = 0; jj < 32; jj += 4) {
            int j = q * 32 + jj;
            float4 yv  = *reinterpret_cast<const float4*>(smY + r * HS_STRIDE + j);
            float4 by4 = *reinterpret_cast<const float4*>(b_y + j);
            yv.x += by4.x; yv.y += by4.y; yv.z += by4.z; yv.w += by4.w;
            *reinterpret_cast<float4*>(out_y + rg * 128 + j) = yv;
        }
    }
}

// ---------------------------------------------------------------------------
extern "C" void kernel_launch(void* const* d_in, const int* in_sizes, int n_in,
                              void* d_out, int out_size) {
    const float* x      = (const float*)d_in[0];
    const float* hidden = (const float*)d_in[1];
    const float* cell   = (const float*)d_in[2];
    const float* W_i    = (const float*)d_in[3];
    const float* b_i    = (const float*)d_in[4];
    const float* W_f    = (const float*)d_in[5];
    const float* b_f    = (const float*)d_in[6];
    const float* W_o    = (const float*)d_in[7];
    const float* b_o    = (const float*)d_in[8];
    const float* W_g    = (const float*)d_in[9];
    const float* b_g    = (const float*)d_in[10];
    const float* W_y    = (const float*)d_in[11];
    const float* b_y    = (const float*)d_in[12];
    float* out = (float*)d_out;

    cudaFuncSetAttribute(lstm_fused_kernel,
                         cudaFuncAttributeMaxDynamicSharedMemorySize, SMEM_BYTES);

    const int prep_elems = N_GATES * K_DIM + H_DIM * H_DIM;
    prep_kernel<<<(prep_elems + 255) / 256, 256>>>(W_i, W_f, W_o, W_g, W_y);

    lstm_fused_kernel<<<B_ROWS / M_TILE, 256, SMEM_BYTES>>>(
        x, hidden, cell, b_i, b_f, b_o, b_g, b_y, out);
}